// round 12
// baseline (speedup 1.0000x reference)
#include <cuda_runtime.h>
#include <cstdint>

// Problem dims (fixed by the dataset)
#define HH   256
#define WW   256
#define NWF  129                 // W/2+1
#define FREQ (HH*NWF)            // 33024 frequency bins
#define NB   16                  // batch
#define NC   32                  // in channels
#define NO   32                  // out channels

// Frequency-domain scratch, layout [img][wf][h]  (h contiguous!)
__device__ float2 g_Xf[NB*NC*FREQ];   // 135 MB
__device__ float2 g_Kf[NO*NC*FREQ];   // 270 MB
__device__ float2 g_Of[NB*NO*FREQ];   // 135 MB
__device__ float2 g_tw[256];          // forward twiddles e^{-2pi i k/256}

// ---------------------------------------------------------------------------
__global__ void init_tw_kernel() {
    int k = threadIdx.x;
    double s, c;
    sincospi((double)k / 128.0, &s, &c);   // angle = 2*pi*k/256
    g_tw[k] = make_float2((float)c, (float)(-s));
}

// ---------------------------------------------------------------------------
__device__ __forceinline__ float2 cadd(float2 a, float2 b) {
    return make_float2(a.x + b.x, a.y + b.y);
}
__device__ __forceinline__ float2 csub(float2 a, float2 b) {
    return make_float2(a.x - b.x, a.y - b.y);
}
__device__ __forceinline__ float2 cmul(float2 a, float2 b) {
    return make_float2(a.x*b.x - a.y*b.y, a.x*b.y + a.y*b.x);
}
__device__ __forceinline__ float2 cmulc(float2 a, float2 w) {  // a*conj(w)
    return make_float2(a.x*w.x + a.y*w.y, a.y*w.x - a.x*w.y);
}
template<int INV>
__device__ __forceinline__ float2 mul_mi(float2 a) {
    return INV ? make_float2(-a.y, a.x) : make_float2(a.y, -a.x);
}

// ---------------------------------------------------------------------------
// 8-point DFT in registers, natural order in/out. INV=1 => conj-DFT (=8*IDFT).
// ---------------------------------------------------------------------------
template<int INV>
__device__ __forceinline__ void fft8(float2 a[8]) {
    float2 s0 = cadd(a[0], a[4]), d0 = csub(a[0], a[4]);
    float2 s1 = cadd(a[2], a[6]), d1 = csub(a[2], a[6]);
    float2 e0 = cadd(s0, s1);
    float2 e2 = csub(s0, s1);
    float2 d1i = mul_mi<INV>(d1);
    float2 e1 = cadd(d0, d1i);
    float2 e3 = csub(d0, d1i);
    float2 t0 = cadd(a[1], a[5]), u0 = csub(a[1], a[5]);
    float2 t1 = cadd(a[3], a[7]), u1 = csub(a[3], a[7]);
    float2 o0 = cadd(t0, t1);
    float2 o2 = csub(t0, t1);
    float2 u1i = mul_mi<INV>(u1);
    float2 o1 = cadd(u0, u1i);
    float2 o3 = csub(u0, u1i);
    const float s = 0.70710678118654752f;
    float2 w1o1 = INV ? make_float2(s*(o1.x - o1.y), s*(o1.y + o1.x))
                      : make_float2(s*(o1.x + o1.y), s*(o1.y - o1.x));
    float2 w2o2 = mul_mi<INV>(o2);
    float2 w3o3 = INV ? make_float2(s*(-o3.x - o3.y), s*( o3.x - o3.y))
                      : make_float2(s*(-o3.x + o3.y), s*(-o3.x - o3.y));
    a[0] = cadd(e0, o0);   a[4] = csub(e0, o0);
    a[1] = cadd(e1, w1o1); a[5] = csub(e1, w1o1);
    a[2] = cadd(e2, w2o2); a[6] = csub(e2, w2o2);
    a[3] = cadd(e3, w3o3); a[7] = csub(e3, w3o3);
}

// ---------------------------------------------------------------------------
// Warp-cooperative 256-pt FFT. Entry: a[n1] = x[32*n1 + lane].
// Exit:  a[k1] = X[8*brev5(lane) + k1].
// ---------------------------------------------------------------------------
template<int INV>
__device__ __forceinline__ void warp_fft256(float2 a[8], int lane,
                                            const float2* tw) {
    fft8<INV>(a);
    #pragma unroll
    for (int k1 = 1; k1 < 8; k1++) {
        float2 w = tw[lane * k1];
        if (INV) w.y = -w.y;
        a[k1] = cmul(a[k1], w);
    }
    #pragma unroll
    for (int st = 0; st < 5; st++) {
        const int h = 16 >> st;
        int j = lane & (h - 1);
        float2 w = tw[j * (128 / h)];
        if (INV) w.y = -w.y;
        bool upper = (lane & h) != 0;
        #pragma unroll
        for (int r = 0; r < 8; r++) {
            float px = __shfl_xor_sync(0xffffffffu, a[r].x, h);
            float py = __shfl_xor_sync(0xffffffffu, a[r].y, h);
            if (upper) {
                float2 d = make_float2(px - a[r].x, py - a[r].y);
                a[r] = (h == 1) ? d : cmul(d, w);
            } else {
                a[r].x += px;
                a[r].y += py;
            }
        }
    }
}

// ---------------------------------------------------------------------------
// Exact mirror-inverse of warp_fft256<0>: consumes the forward's register
// layout (a[k1] at lane), returns natural order a[n1]=x[32*n1+lane], times 256.
// ---------------------------------------------------------------------------
__device__ __forceinline__ void warp_ifft256_rev(float2 a[8], int lane,
                                                 const float2* tw) {
    #pragma unroll
    for (int st = 0; st < 5; st++) {
        const int h = 1 << st;
        int j = lane & (h - 1);
        float2 w = tw[j * (128 / h)];
        bool upper = (lane & h) != 0;
        #pragma unroll
        for (int r = 0; r < 8; r++) {
            if (upper && h > 1) a[r] = cmulc(a[r], w);   // de-twiddle
            float px = __shfl_xor_sync(0xffffffffu, a[r].x, h);
            float py = __shfl_xor_sync(0xffffffffu, a[r].y, h);
            if (upper) a[r] = make_float2(px - a[r].x, py - a[r].y);
            else       { a[r].x += px; a[r].y += py; }
        }
    }
    #pragma unroll
    for (int k1 = 1; k1 < 8; k1++)
        a[k1] = cmulc(a[k1], tw[lane * k1]);
    fft8<1>(a);
}

// ---------------------------------------------------------------------------
// Forward real FFT along W + transposed write to [wf][h] layout.
// Block = 256 thr (8 warps = 8 row-pairs = 16 rows). grid = nimg*16.
// ---------------------------------------------------------------------------
__global__ void __launch_bounds__(256)
rfft_rows_kernel(const float* __restrict__ in, float2* __restrict__ outf) {
    __shared__ float2 Sz[8*264];          // per-warp [k1][kr] (stride 33)
    __shared__ __align__(16) float2 Sout[129*16];   // [k][16 rows]
    __shared__ float2 tw[256];
    const int t = threadIdx.x, w = t >> 5, lane = t & 31;
    tw[t] = g_tw[t];
    const int n  = blockIdx.x >> 4;
    const int r0 = (blockIdx.x & 15) << 4;          // 16 rows per block
    const float* rowA = in + ((size_t)n*HH + r0 + 2*w) * WW;
    float2 a[8];
    #pragma unroll
    for (int n1 = 0; n1 < 8; n1++) {
        int i = 32*n1 + lane;
        a[n1] = make_float2(rowA[i], rowA[WW + i]);
    }
    __syncthreads();                      // tw ready
    warp_fft256<0>(a, lane, tw);
    float2* S = Sz + w * 264;
    const int kr = __brev(lane) >> 27;
    #pragma unroll
    for (int k1 = 0; k1 < 8; k1++)
        S[k1*33 + kr] = a[k1];
    __syncthreads();
    // unpack pairs -> Sout[k][2p],[2p+1] as one float4
    float4* Sout4 = (float4*)Sout;
    for (int idx = t; idx < 129*8; idx += 256) {
        int k = idx >> 3, p = idx & 7;
        int kn = (256 - k) & 255;
        const float2* Sp = Sz + p * 264;
        float2 Zk = Sp[(k  & 7)*33 + (k  >> 3)];
        float2 Zn = Sp[(kn & 7)*33 + (kn >> 3)];
        float4 v;
        v.x = 0.5f*(Zk.x + Zn.x); v.y = 0.5f*(Zk.y - Zn.y);   // A (row 2p)
        v.z = 0.5f*(Zk.y + Zn.y); v.w = 0.5f*(Zn.x - Zk.x);   // B (row 2p+1)
        Sout4[k*8 + p] = v;
    }
    __syncthreads();
    // coalesced transposed write: out[n][k][r0..r0+15]
    float4* dst = (float4*)(outf + (size_t)n*FREQ + r0);
    for (int idx = t; idx < 129*8; idx += 256) {
        int k = idx >> 3, cp = idx & 7;
        dst[(size_t)k*(HH/2) + cp] = Sout4[k*8 + cp];
    }
}

// ---------------------------------------------------------------------------
// Column-direction FFT, [wf][h] layout: pure streaming, registers + shuffles.
// Stores scrambled order row[32*k1+lane]=a[k1] (einsum is bin-agnostic).
// ---------------------------------------------------------------------------
__global__ void __launch_bounds__(256)
fft_cols_fwd_kernel(float2* __restrict__ data) {
    __shared__ float2 tw[256];
    const int t = threadIdx.x, w = t >> 5, lane = t & 31;
    tw[t] = g_tw[t];
    __syncthreads();
    const int n  = blockIdx.x / 17;
    const int wf = (blockIdx.x % 17) * 8 + w;
    if (wf > 128) return;
    float2* row = data + (size_t)n*FREQ + (size_t)wf*HH;
    float2 a[8];
    #pragma unroll
    for (int n1 = 0; n1 < 8; n1++) a[n1] = row[32*n1 + lane];
    warp_fft256<0>(a, lane, tw);
    #pragma unroll
    for (int k1 = 0; k1 < 8; k1++) row[32*k1 + lane] = a[k1];
}

// ---------------------------------------------------------------------------
// Inverse column FFT consuming the scrambled order; natural order out.
// ---------------------------------------------------------------------------
__global__ void __launch_bounds__(256)
fft_cols_inv_kernel(float2* __restrict__ data, float scale) {
    __shared__ float2 tw[256];
    const int t = threadIdx.x, w = t >> 5, lane = t & 31;
    tw[t] = g_tw[t];
    __syncthreads();
    const int n  = blockIdx.x / 17;
    const int wf = (blockIdx.x % 17) * 8 + w;
    if (wf > 128) return;
    float2* row = data + (size_t)n*FREQ + (size_t)wf*HH;
    float2 a[8];
    #pragma unroll
    for (int k1 = 0; k1 < 8; k1++) a[k1] = row[32*k1 + lane];
    warp_ifft256_rev(a, lane, tw);
    #pragma unroll
    for (int n1 = 0; n1 < 8; n1++) {
        float2 v = a[n1];
        row[32*n1 + lane] = make_float2(v.x*scale, v.y*scale);
    }
}

// ---------------------------------------------------------------------------
// cp.async helpers (8-byte variant: matches the float2 staging layout)
// ---------------------------------------------------------------------------
__device__ __forceinline__ void cp8(void* dst_smem, const void* src_gmem) {
    unsigned d = (unsigned)__cvta_generic_to_shared(dst_smem);
    asm volatile("cp.async.ca.shared.global [%0], [%1], 8;"
                 :: "r"(d), "l"(src_gmem));
}
#define CP_COMMIT() asm volatile("cp.async.commit_group;" ::: "memory")
#define CP_WAIT0()  asm volatile("cp.async.wait_group 0;"  ::: "memory")

// ---------------------------------------------------------------------------
// Tensor-core einsum: Of[b,o,f] = sum_c Xf[b,c,f] * Kf[o,c,f]
// f-tile = 16 (full 128B lines). Round-9 staging layout (conflict-free
// fragment LDS), double-buffered via cp.async.ca 8B. Register-side tf32
// hi/lo split; negation trick for real part.
// ---------------------------------------------------------------------------
__device__ __forceinline__ void split2u(float v, unsigned& h, unsigned& l) {
    unsigned hv = __float_as_uint(v) & 0xFFFFE000u;
    float lf = v - __uint_as_float(hv);
    h = hv;
    l = __float_as_uint(lf) & 0xFFFFE000u;
}

#define MMA8(D, A, B)                                                        \
    asm volatile("mma.sync.aligned.m16n8k8.row.col.f32.tf32.tf32.f32 "       \
                 "{%0,%1,%2,%3},{%4,%5,%6,%7},{%8,%9},{%0,%1,%2,%3};"        \
                 : "+f"(D[0]), "+f"(D[1]), "+f"(D[2]), "+f"(D[3])            \
                 : "r"(A[0]), "r"(A[1]), "r"(A[2]), "r"(A[3]),               \
                   "r"(B[0]), "r"(B[1]))

__global__ void __launch_bounds__(256, 2)
einsum_tc_kernel(const float2* __restrict__ Xf,
                 const float2* __restrict__ Kf,
                 float2* __restrict__ Of) {
    // dynamic smem: 2 stages x 6144 float2 = 96 KB
    // stage s base = SB2 + s*6144:
    //   XS at +0    : [r(4)][f(16)][ln(32)]    2048 float2
    //   KS at +2048 : [slot(8)][f(16)][ln(32)] 4096 float2
    extern __shared__ __align__(16) float2 SB2[];

    const int t    = threadIdx.x;
    const int w    = t >> 5;
    const int lane = t & 31;
    const int f0   = blockIdx.x * 16;

    float Pre[2][4][4], Pim[2][4][4];
    #pragma unroll
    for (int bin = 0; bin < 2; bin++)
        #pragma unroll
        for (int ot = 0; ot < 4; ot++)
            #pragma unroll
            for (int j = 0; j < 4; j++) {
                Pre[bin][ot][j] = 0.f;
                Pim[bin][ot][j] = 0.f;
            }

    // loader roles (identical to round-9)
    const int cl   = t & 7;
    const int bx   = t >> 3;                       // X row b (t<128), K row o
    const int ln   = ((bx & 7) << 2) | (cl & 3);
    const int rX   = (bx >> 3) | ((cl >> 2) << 1); // a-frag slot 0..3
    const int slotK = (bx >> 3)*2 + (cl >> 2);     // 0..7

    // per-thread gmem cursors (advance by 8*FREQ per chunk)
    const float2* xsrc = Xf + ((size_t)(bx*NC + cl))*FREQ + f0;
    const float2* ksrc = Kf + ((size_t)(bx*NC + cl))*FREQ + f0;

    // issue stage 0
    {
        float2* XS = SB2;
        float2* KS = SB2 + 2048;
        if (t < 128) {
            #pragma unroll
            for (int q = 0; q < 16; q++)
                cp8(&XS[(rX*16 + q)*32 + ln], xsrc + q);
        }
        #pragma unroll
        for (int q = 0; q < 16; q++)
            cp8(&KS[(slotK*16 + q)*32 + ln], ksrc + q);
        CP_COMMIT();
        xsrc += (size_t)8*FREQ;
        ksrc += (size_t)8*FREQ;
    }

    for (int cs = 0; cs < 4; cs++) {
        CP_WAIT0();
        __syncthreads();             // stage cs visible; prev compute done
        if (cs < 3) {                // issue stage cs+1 into the other buffer
            float2* XS = SB2 + ((cs + 1) & 1)*6144;
            float2* KS = XS + 2048;
            if (t < 128) {
                #pragma unroll
                for (int q = 0; q < 16; q++)
                    cp8(&XS[(rX*16 + q)*32 + ln], xsrc + q);
            }
            #pragma unroll
            for (int q = 0; q < 16; q++)
                cp8(&KS[(slotK*16 + q)*32 + ln], ksrc + q);
            CP_COMMIT();
            xsrc += (size_t)8*FREQ;
            ksrc += (size_t)8*FREQ;
        }
        // compute on stage cs (round-9 fragment reads, conflict-free)
        const float2* XS = SB2 + (cs & 1)*6144;
        const float2* KS = XS + 2048;
        #pragma unroll
        for (int bin = 0; bin < 2; bin++) {
            const int f = w + 8*bin;
            unsigned arh[4], arl[4], aih[4], ail[4];
            #pragma unroll
            for (int r = 0; r < 4; r++) {
                float2 v = XS[(r*16 + f)*32 + lane];
                split2u(v.x, arh[r], arl[r]);
                split2u(v.y, aih[r], ail[r]);
            }
            #pragma unroll
            for (int ot = 0; ot < 4; ot++) {
                unsigned brh[2], brl[2], bih[2], bil[2], nbh[2], nbl[2];
                #pragma unroll
                for (int r = 0; r < 2; r++) {
                    float2 v = KS[((ot*2 + r)*16 + f)*32 + lane];
                    split2u(v.x, brh[r], brl[r]);
                    split2u(v.y, bih[r], bil[r]);
                    nbh[r] = bih[r] ^ 0x80000000u;
                    nbl[r] = bil[r] ^ 0x80000000u;
                }
                MMA8(Pre[bin][ot], arh, brh);
                MMA8(Pre[bin][ot], arh, brl);
                MMA8(Pre[bin][ot], arl, brh);
                MMA8(Pre[bin][ot], aih, nbh);
                MMA8(Pre[bin][ot], aih, nbl);
                MMA8(Pre[bin][ot], ail, nbh);
                MMA8(Pim[bin][ot], arh, bih);
                MMA8(Pim[bin][ot], arh, bil);
                MMA8(Pim[bin][ot], arl, bih);
                MMA8(Pim[bin][ot], aih, brh);
                MMA8(Pim[bin][ot], aih, brl);
                MMA8(Pim[bin][ot], ail, brh);
            }
        }
    }
    __syncthreads();                 // all fragment reads done
    // stage output: OS[rc][f ^ s(rc)], s spreads bank-pairs (2-way max)
    float2* OS = SB2;                // 64 KB of the 96 KB buffer
    #pragma unroll
    for (int bin = 0; bin < 2; bin++) {
        const int f = w + 8*bin;
        #pragma unroll
        for (int ot = 0; ot < 4; ot++)
            #pragma unroll
            for (int j = 0; j < 4; j++) {
                int row = (lane >> 2) + 8*(j >> 1);          // b
                int col = ot*8 + 2*(lane & 3) + (j & 1);     // o
                int rc  = row*32 + col;
                int s   = (((rc >> 5) & 7) << 1) | ((rc >> 1) & 1);
                OS[rc*16 + (f ^ s)] =
                    make_float2(Pre[bin][ot][j], Pim[bin][ot][j]);
            }
    }
    __syncthreads();
    // full-line coalesced store: 512 rows x 16 bins (128B per row)
    for (int idx = t; idx < 8192; idx += 256) {
        int rc = idx >> 4, f = idx & 15;
        int s  = (((rc >> 5) & 7) << 1) | ((rc >> 1) & 1);
        Of[(size_t)rc*FREQ + f0 + f] = OS[rc*16 + (f ^ s)];
    }
}

// ---------------------------------------------------------------------------
// Inverse real FFT along W from [wf][h] layout; real rows out. grid=nimg*16.
// ---------------------------------------------------------------------------
__global__ void __launch_bounds__(256)
irfft_rows_kernel(const float2* __restrict__ inf, float* __restrict__ out) {
    __shared__ __align__(16) float2 Sload[129*18];  // [k][16 rows], stride 18
    __shared__ float2 Sz[8*264];
    __shared__ float2 tw[256];
    const int t = threadIdx.x, w = t >> 5, lane = t & 31;
    tw[t] = g_tw[t];
    const int n  = blockIdx.x >> 4;
    const int r0 = (blockIdx.x & 15) << 4;
    // coalesced gather of [k][r0..r0+15]
    const float4* src = (const float4*)(inf + (size_t)n*FREQ + r0);
    float4* Sload4 = (float4*)Sload;
    for (int idx = t; idx < 129*8; idx += 256) {
        int k = idx >> 3, cp = idx & 7;
        Sload4[k*9 + cp] = src[(size_t)k*(HH/2) + cp];
    }
    __syncthreads();
    // build Z for pair p=w: rows r0+2w (A), r0+2w+1 (B)
    float2 a[8];
    #pragma unroll
    for (int n1 = 0; n1 < 8; n1++) {
        int i = 32*n1 + lane;
        if (i <= 128) {
            float2 A  = Sload[i*18 + 2*w];
            float2 Bv = Sload[i*18 + 2*w + 1];
            a[n1] = make_float2(A.x - Bv.y, A.y + Bv.x);
        } else {
            int kn = 256 - i;
            float2 A  = Sload[kn*18 + 2*w];
            float2 Bv = Sload[kn*18 + 2*w + 1];
            a[n1] = make_float2(A.x + Bv.y, Bv.x - A.y);
        }
    }
    warp_fft256<1>(a, lane, tw);
    float2* S = Sz + w * 264;
    const int kr = __brev(lane) >> 27;
    const float sc = 1.0f/256.0f;
    #pragma unroll
    for (int k1 = 0; k1 < 8; k1++) {
        float2 v = a[k1];
        S[k1*33 + kr] = make_float2(v.x*sc, v.y*sc);
    }
    __syncwarp();
    float* oA = out + ((size_t)n*HH + r0 + 2*w) * WW;
    #pragma unroll
    for (int m = 0; m < 8; m++) {
        int i = lane + 32*m;
        float2 v = S[(i & 7)*33 + (i >> 3)];
        oA[i]      = v.x;
        oA[WW + i] = v.y;
    }
}

// ---------------------------------------------------------------------------
extern "C" void kernel_launch(void* const* d_in, const int* in_sizes, int n_in,
                              void* d_out, int out_size) {
    const float* x = (const float*)d_in[0];   // (16,32,256,256)
    const float* w = (const float*)d_in[1];   // (32,32,256,256)
    float* out = (float*)d_out;               // (16,32,256,256)

    float2 *Xf, *Kf, *Of;
    cudaGetSymbolAddress((void**)&Xf, g_Xf);
    cudaGetSymbolAddress((void**)&Kf, g_Kf);
    cudaGetSymbolAddress((void**)&Of, g_Of);

    cudaFuncSetAttribute(einsum_tc_kernel,
                         cudaFuncAttributeMaxDynamicSharedMemorySize, 98304);

    init_tw_kernel<<<1, 256>>>();

    // forward row FFTs (transposed write)
    rfft_rows_kernel<<<NB*NC*16, 256>>>(x, Xf);
    rfft_rows_kernel<<<NO*NC*16, 256>>>(w, Kf);
    // forward column FFTs (streaming, scrambled bin order)
    fft_cols_fwd_kernel<<<NB*NC*17, 256>>>(Xf);
    fft_cols_fwd_kernel<<<NO*NC*17, 256>>>(Kf);

    // frequency-domain channel contraction (cp.async 8B pipelined, r9 layout)
    einsum_tc_kernel<<<FREQ/16, 256, 98304>>>(Xf, Kf, Of);

    // inverse column FFT (consumes scrambled order, 1/256)
    fft_cols_inv_kernel<<<NB*NO*17, 256>>>(Of, 1.0f/256.0f);
    // inverse row FFT (gathers transposed layout, final 1/256)
    irfft_rows_kernel<<<NB*NO*16, 256>>>(Of, out);
}

// round 15
// speedup vs baseline: 1.0977x; 1.0977x over previous
#include <cuda_runtime.h>
#include <cstdint>

// Problem dims (fixed by the dataset)
#define HH   256
#define WW   256
#define NWF  129                 // W/2+1
#define FREQ (HH*NWF)            // 33024 frequency bins
#define NB   16                  // batch
#define NC   32                  // in channels
#define NO   32                  // out channels

// Frequency-domain scratch, layout [img][wf][h]  (h contiguous!)
__device__ float2 g_Xf[NB*NC*FREQ];   // 135 MB
__device__ float2 g_Kf[NO*NC*FREQ];   // 270 MB
__device__ float2 g_Of[NB*NO*FREQ];   // 135 MB
__device__ float2 g_tw[256];          // forward twiddles e^{-2pi i k/256}

// ---------------------------------------------------------------------------
__global__ void init_tw_kernel() {
    int k = threadIdx.x;
    double s, c;
    sincospi((double)k / 128.0, &s, &c);   // angle = 2*pi*k/256
    g_tw[k] = make_float2((float)c, (float)(-s));
}

// ---------------------------------------------------------------------------
__device__ __forceinline__ float2 cadd(float2 a, float2 b) {
    return make_float2(a.x + b.x, a.y + b.y);
}
__device__ __forceinline__ float2 csub(float2 a, float2 b) {
    return make_float2(a.x - b.x, a.y - b.y);
}
__device__ __forceinline__ float2 cmul(float2 a, float2 b) {
    return make_float2(a.x*b.x - a.y*b.y, a.x*b.y + a.y*b.x);
}
__device__ __forceinline__ float2 cmulc(float2 a, float2 w) {  // a*conj(w)
    return make_float2(a.x*w.x + a.y*w.y, a.y*w.x - a.x*w.y);
}
template<int INV>
__device__ __forceinline__ float2 mul_mi(float2 a) {
    return INV ? make_float2(-a.y, a.x) : make_float2(a.y, -a.x);
}

// ---------------------------------------------------------------------------
// 8-point DFT in registers, natural order in/out. INV=1 => conj-DFT (=8*IDFT).
// ---------------------------------------------------------------------------
template<int INV>
__device__ __forceinline__ void fft8(float2 a[8]) {
    float2 s0 = cadd(a[0], a[4]), d0 = csub(a[0], a[4]);
    float2 s1 = cadd(a[2], a[6]), d1 = csub(a[2], a[6]);
    float2 e0 = cadd(s0, s1);
    float2 e2 = csub(s0, s1);
    float2 d1i = mul_mi<INV>(d1);
    float2 e1 = cadd(d0, d1i);
    float2 e3 = csub(d0, d1i);
    float2 t0 = cadd(a[1], a[5]), u0 = csub(a[1], a[5]);
    float2 t1 = cadd(a[3], a[7]), u1 = csub(a[3], a[7]);
    float2 o0 = cadd(t0, t1);
    float2 o2 = csub(t0, t1);
    float2 u1i = mul_mi<INV>(u1);
    float2 o1 = cadd(u0, u1i);
    float2 o3 = csub(u0, u1i);
    const float s = 0.70710678118654752f;
    float2 w1o1 = INV ? make_float2(s*(o1.x - o1.y), s*(o1.y + o1.x))
                      : make_float2(s*(o1.x + o1.y), s*(o1.y - o1.x));
    float2 w2o2 = mul_mi<INV>(o2);
    float2 w3o3 = INV ? make_float2(s*(-o3.x - o3.y), s*( o3.x - o3.y))
                      : make_float2(s*(-o3.x + o3.y), s*(-o3.x - o3.y));
    a[0] = cadd(e0, o0);   a[4] = csub(e0, o0);
    a[1] = cadd(e1, w1o1); a[5] = csub(e1, w1o1);
    a[2] = cadd(e2, w2o2); a[6] = csub(e2, w2o2);
    a[3] = cadd(e3, w3o3); a[7] = csub(e3, w3o3);
}

// ---------------------------------------------------------------------------
// Warp-cooperative 256-pt FFT. Entry: a[n1] = x[32*n1 + lane].
// Exit:  a[k1] = X[8*brev5(lane) + k1].
// ---------------------------------------------------------------------------
template<int INV>
__device__ __forceinline__ void warp_fft256(float2 a[8], int lane,
                                            const float2* tw) {
    fft8<INV>(a);
    #pragma unroll
    for (int k1 = 1; k1 < 8; k1++) {
        float2 w = tw[lane * k1];
        if (INV) w.y = -w.y;
        a[k1] = cmul(a[k1], w);
    }
    #pragma unroll
    for (int st = 0; st < 5; st++) {
        const int h = 16 >> st;
        int j = lane & (h - 1);
        float2 w = tw[j * (128 / h)];
        if (INV) w.y = -w.y;
        bool upper = (lane & h) != 0;
        #pragma unroll
        for (int r = 0; r < 8; r++) {
            float px = __shfl_xor_sync(0xffffffffu, a[r].x, h);
            float py = __shfl_xor_sync(0xffffffffu, a[r].y, h);
            if (upper) {
                float2 d = make_float2(px - a[r].x, py - a[r].y);
                a[r] = (h == 1) ? d : cmul(d, w);
            } else {
                a[r].x += px;
                a[r].y += py;
            }
        }
    }
}

// ---------------------------------------------------------------------------
// Exact mirror-inverse of warp_fft256<0>: consumes the forward's register
// layout (a[k1] at lane), returns natural order a[n1]=x[32*n1+lane], times 256.
// ---------------------------------------------------------------------------
__device__ __forceinline__ void warp_ifft256_rev(float2 a[8], int lane,
                                                 const float2* tw) {
    #pragma unroll
    for (int st = 0; st < 5; st++) {
        const int h = 1 << st;
        int j = lane & (h - 1);
        float2 w = tw[j * (128 / h)];
        bool upper = (lane & h) != 0;
        #pragma unroll
        for (int r = 0; r < 8; r++) {
            if (upper && h > 1) a[r] = cmulc(a[r], w);   // de-twiddle
            float px = __shfl_xor_sync(0xffffffffu, a[r].x, h);
            float py = __shfl_xor_sync(0xffffffffu, a[r].y, h);
            if (upper) a[r] = make_float2(px - a[r].x, py - a[r].y);
            else       { a[r].x += px; a[r].y += py; }
        }
    }
    #pragma unroll
    for (int k1 = 1; k1 < 8; k1++)
        a[k1] = cmulc(a[k1], tw[lane * k1]);
    fft8<1>(a);
}

// ---------------------------------------------------------------------------
// Forward real FFT along W + transposed write to [wf][h] layout.
// Block = 256 thr (8 warps = 8 row-pairs = 16 rows). grid = nimg*16.
// ---------------------------------------------------------------------------
__global__ void __launch_bounds__(256)
rfft_rows_kernel(const float* __restrict__ in, float2* __restrict__ outf) {
    __shared__ float2 Sz[8*264];          // per-warp [k1][kr] (stride 33)
    __shared__ __align__(16) float2 Sout[129*16];   // [k][16 rows]
    __shared__ float2 tw[256];
    const int t = threadIdx.x, w = t >> 5, lane = t & 31;
    tw[t] = g_tw[t];
    const int n  = blockIdx.x >> 4;
    const int r0 = (blockIdx.x & 15) << 4;          // 16 rows per block
    const float* rowA = in + ((size_t)n*HH + r0 + 2*w) * WW;
    float2 a[8];
    #pragma unroll
    for (int n1 = 0; n1 < 8; n1++) {
        int i = 32*n1 + lane;
        a[n1] = make_float2(rowA[i], rowA[WW + i]);
    }
    __syncthreads();                      // tw ready
    warp_fft256<0>(a, lane, tw);
    float2* S = Sz + w * 264;
    const int kr = __brev(lane) >> 27;
    #pragma unroll
    for (int k1 = 0; k1 < 8; k1++)
        S[k1*33 + kr] = a[k1];
    __syncthreads();
    // unpack pairs -> Sout[k][2p],[2p+1] as one float4
    float4* Sout4 = (float4*)Sout;
    for (int idx = t; idx < 129*8; idx += 256) {
        int k = idx >> 3, p = idx & 7;
        int kn = (256 - k) & 255;
        const float2* Sp = Sz + p * 264;
        float2 Zk = Sp[(k  & 7)*33 + (k  >> 3)];
        float2 Zn = Sp[(kn & 7)*33 + (kn >> 3)];
        float4 v;
        v.x = 0.5f*(Zk.x + Zn.x); v.y = 0.5f*(Zk.y - Zn.y);   // A (row 2p)
        v.z = 0.5f*(Zk.y + Zn.y); v.w = 0.5f*(Zn.x - Zk.x);   // B (row 2p+1)
        Sout4[k*8 + p] = v;
    }
    __syncthreads();
    // coalesced transposed write: out[n][k][r0..r0+15]
    float4* dst = (float4*)(outf + (size_t)n*FREQ + r0);
    for (int idx = t; idx < 129*8; idx += 256) {
        int k = idx >> 3, cp = idx & 7;
        dst[(size_t)k*(HH/2) + cp] = Sout4[k*8 + cp];
    }
}

// ---------------------------------------------------------------------------
// Column-direction FFT, [wf][h] layout: pure streaming, registers + shuffles.
// Stores scrambled order row[32*k1+lane]=a[k1] (einsum is bin-agnostic).
// ---------------------------------------------------------------------------
__global__ void __launch_bounds__(256)
fft_cols_fwd_kernel(float2* __restrict__ data) {
    __shared__ float2 tw[256];
    const int t = threadIdx.x, w = t >> 5, lane = t & 31;
    tw[t] = g_tw[t];
    __syncthreads();
    const int n  = blockIdx.x / 17;
    const int wf = (blockIdx.x % 17) * 8 + w;
    if (wf > 128) return;
    float2* row = data + (size_t)n*FREQ + (size_t)wf*HH;
    float2 a[8];
    #pragma unroll
    for (int n1 = 0; n1 < 8; n1++) a[n1] = row[32*n1 + lane];
    warp_fft256<0>(a, lane, tw);
    #pragma unroll
    for (int k1 = 0; k1 < 8; k1++) row[32*k1 + lane] = a[k1];
}

// ---------------------------------------------------------------------------
// Inverse column FFT consuming the scrambled order; natural order out.
// ---------------------------------------------------------------------------
__global__ void __launch_bounds__(256)
fft_cols_inv_kernel(float2* __restrict__ data, float scale) {
    __shared__ float2 tw[256];
    const int t = threadIdx.x, w = t >> 5, lane = t & 31;
    tw[t] = g_tw[t];
    __syncthreads();
    const int n  = blockIdx.x / 17;
    const int wf = (blockIdx.x % 17) * 8 + w;
    if (wf > 128) return;
    float2* row = data + (size_t)n*FREQ + (size_t)wf*HH;
    float2 a[8];
    #pragma unroll
    for (int k1 = 0; k1 < 8; k1++) a[k1] = row[32*k1 + lane];
    warp_ifft256_rev(a, lane, tw);
    #pragma unroll
    for (int n1 = 0; n1 < 8; n1++) {
        float2 v = a[n1];
        row[32*n1 + lane] = make_float2(v.x*scale, v.y*scale);
    }
}

// ---------------------------------------------------------------------------
// Tensor-core einsum: Of[b,o,f] = sum_c Xf[b,c,f] * Kf[o,c,f]
// f-tile = 16 (full 128B lines). 512 threads, 16 warps, ONE bin per warp.
// Round-9 staging layout + fragment math (conflict-free LDS); no cp.async.
// Register-side tf32 hi/lo split; negation trick for real part.
// ---------------------------------------------------------------------------
__device__ __forceinline__ void split2u(float v, unsigned& h, unsigned& l) {
    unsigned hv = __float_as_uint(v) & 0xFFFFE000u;
    float lf = v - __uint_as_float(hv);
    h = hv;
    l = __float_as_uint(lf) & 0xFFFFE000u;
}

#define MMA8(D, A, B)                                                        \
    asm volatile("mma.sync.aligned.m16n8k8.row.col.f32.tf32.tf32.f32 "       \
                 "{%0,%1,%2,%3},{%4,%5,%6,%7},{%8,%9},{%0,%1,%2,%3};"        \
                 : "+f"(D[0]), "+f"(D[1]), "+f"(D[2]), "+f"(D[3])            \
                 : "r"(A[0]), "r"(A[1]), "r"(A[2]), "r"(A[3]),               \
                   "r"(B[0]), "r"(B[1]))

__global__ void __launch_bounds__(512, 2)
einsum_tc_kernel(const float2* __restrict__ Xf,
                 const float2* __restrict__ Kf,
                 float2* __restrict__ Of) {
    // dynamic smem 64 KB:
    //   staging: XS [r(4)][f(16)][ln(32)] 2048 float2 (16 KB)
    //            KS [slot(8)][f(16)][ln(32)] 4096 float2 (32 KB)
    //   reused as OS float2[512 rc][16 f] (64 KB) in epilogue
    extern __shared__ __align__(16) float2 SB2[];
    float2* XS = SB2;
    float2* KS = SB2 + 2048;

    const int t    = threadIdx.x;          // 0..511
    const int w    = t >> 5;               // warp = bin f (0..15)
    const int lane = t & 31;
    const int f0   = blockIdx.x * 16;

    float Pre[4][4], Pim[4][4];
    #pragma unroll
    for (int ot = 0; ot < 4; ot++)
        #pragma unroll
        for (int j = 0; j < 4; j++) {
            Pre[ot][j] = 0.f;
            Pim[ot][j] = 0.f;
        }

    // loader roles: 2 threads per tile row, 4 float4 each
    const int rowX = t >> 1;               // X: valid for t<256 (rows 0..127)
    const int half = t & 1;
    const int bXr  = rowX >> 3, cXr = rowX & 7;
    const int lnX  = ((bXr & 7) << 2) | (cXr & 3);
    const int rX   = (bXr >> 3) | ((cXr >> 2) << 1);
    const int rowK = t >> 1;               // K rows 0..255
    const int oKr  = rowK >> 3, cKr = rowK & 7;
    const int lnK  = ((oKr & 7) << 2) | (cKr & 3);
    const int slotK = (oKr >> 3)*2 + (cKr >> 2);

    for (int cs = 0; cs < 4; cs++) {
        const int c0 = cs * 8;
        __syncthreads();                   // prior compute reads done
        if (t < 256) {                     // X tile: 128 rows x 128B
            const float4* src = (const float4*)
                (Xf + ((size_t)(bXr*NC + c0 + cXr))*FREQ + f0);
            #pragma unroll
            for (int qq = 0; qq < 4; qq++) {
                int q = half*4 + qq;
                float4 v = src[q];
                XS[(rX*16 + 2*q    )*32 + lnX] = make_float2(v.x, v.y);
                XS[(rX*16 + 2*q + 1)*32 + lnX] = make_float2(v.z, v.w);
            }
        }
        {                                  // K tile: 256 rows x 128B
            const float4* src = (const float4*)
                (Kf + ((size_t)(oKr*NC + c0 + cKr))*FREQ + f0);
            #pragma unroll
            for (int qq = 0; qq < 4; qq++) {
                int q = half*4 + qq;
                float4 v = src[q];
                KS[((slotK)*16 + 2*q    )*32 + lnK] = make_float2(v.x, v.y);
                KS[((slotK)*16 + 2*q + 1)*32 + lnK] = make_float2(v.z, v.w);
            }
        }
        __syncthreads();                   // tile visible
        // compute: warp w handles bin f = w
        unsigned arh[4], arl[4], aih[4], ail[4];
        #pragma unroll
        for (int r = 0; r < 4; r++) {
            float2 v = XS[(r*16 + w)*32 + lane];
            split2u(v.x, arh[r], arl[r]);
            split2u(v.y, aih[r], ail[r]);
        }
        #pragma unroll
        for (int ot = 0; ot < 4; ot++) {
            unsigned brh[2], brl[2], bih[2], bil[2], nbh[2], nbl[2];
            #pragma unroll
            for (int r = 0; r < 2; r++) {
                float2 v = KS[((ot*2 + r)*16 + w)*32 + lane];
                split2u(v.x, brh[r], brl[r]);
                split2u(v.y, bih[r], bil[r]);
                nbh[r] = bih[r] ^ 0x80000000u;
                nbl[r] = bil[r] ^ 0x80000000u;
            }
            MMA8(Pre[ot], arh, brh);
            MMA8(Pre[ot], arh, brl);
            MMA8(Pre[ot], arl, brh);
            MMA8(Pre[ot], aih, nbh);
            MMA8(Pre[ot], aih, nbl);
            MMA8(Pre[ot], ail, nbh);
            MMA8(Pim[ot], arh, bih);
            MMA8(Pim[ot], arh, bil);
            MMA8(Pim[ot], arl, bih);
            MMA8(Pim[ot], aih, brh);
            MMA8(Pim[ot], aih, brl);
            MMA8(Pim[ot], ail, brh);
        }
    }
    __syncthreads();                       // all fragment reads done
    // stage output: OS[rc][f ^ s(rc)], s spreads bank-pairs (2-way max)
    float2* OS = SB2;
    #pragma unroll
    for (int ot = 0; ot < 4; ot++)
        #pragma unroll
        for (int j = 0; j < 4; j++) {
            int row = (lane >> 2) + 8*(j >> 1);          // b
            int col = ot*8 + 2*(lane & 3) + (j & 1);     // o
            int rc  = row*32 + col;
            int s   = (((rc >> 5) & 7) << 1) | ((rc >> 1) & 1);
            OS[rc*16 + (w ^ s)] = make_float2(Pre[ot][j], Pim[ot][j]);
        }
    __syncthreads();
    // full-line coalesced store: 512 rows x 16 bins (128B per row)
    for (int idx = t; idx < 8192; idx += 512) {
        int rc = idx >> 4, f = idx & 15;
        int s  = (((rc >> 5) & 7) << 1) | ((rc >> 1) & 1);
        Of[(size_t)rc*FREQ + f0 + f] = OS[rc*16 + (f ^ s)];
    }
}

// ---------------------------------------------------------------------------
// Inverse real FFT along W from [wf][h] layout; real rows out. grid=nimg*16.
// ---------------------------------------------------------------------------
__global__ void __launch_bounds__(256)
irfft_rows_kernel(const float2* __restrict__ inf, float* __restrict__ out) {
    __shared__ __align__(16) float2 Sload[129*18];  // [k][16 rows], stride 18
    __shared__ float2 Sz[8*264];
    __shared__ float2 tw[256];
    const int t = threadIdx.x, w = t >> 5, lane = t & 31;
    tw[t] = g_tw[t];
    const int n  = blockIdx.x >> 4;
    const int r0 = (blockIdx.x & 15) << 4;
    // coalesced gather of [k][r0..r0+15]
    const float4* src = (const float4*)(inf + (size_t)n*FREQ + r0);
    float4* Sload4 = (float4*)Sload;
    for (int idx = t; idx < 129*8; idx += 256) {
        int k = idx >> 3, cp = idx & 7;
        Sload4[k*9 + cp] = src[(size_t)k*(HH/2) + cp];
    }
    __syncthreads();
    // build Z for pair p=w: rows r0+2w (A), r0+2w+1 (B)
    float2 a[8];
    #pragma unroll
    for (int n1 = 0; n1 < 8; n1++) {
        int i = 32*n1 + lane;
        if (i <= 128) {
            float2 A  = Sload[i*18 + 2*w];
            float2 Bv = Sload[i*18 + 2*w + 1];
            a[n1] = make_float2(A.x - Bv.y, A.y + Bv.x);
        } else {
            int kn = 256 - i;
            float2 A  = Sload[kn*18 + 2*w];
            float2 Bv = Sload[kn*18 + 2*w + 1];
            a[n1] = make_float2(A.x + Bv.y, Bv.x - A.y);
        }
    }
    warp_fft256<1>(a, lane, tw);
    float2* S = Sz + w * 264;
    const int kr = __brev(lane) >> 27;
    const float sc = 1.0f/256.0f;
    #pragma unroll
    for (int k1 = 0; k1 < 8; k1++) {
        float2 v = a[k1];
        S[k1*33 + kr] = make_float2(v.x*sc, v.y*sc);
    }
    __syncwarp();
    float* oA = out + ((size_t)n*HH + r0 + 2*w) * WW;
    #pragma unroll
    for (int m = 0; m < 8; m++) {
        int i = lane + 32*m;
        float2 v = S[(i & 7)*33 + (i >> 3)];
        oA[i]      = v.x;
        oA[WW + i] = v.y;
    }
}

// ---------------------------------------------------------------------------
extern "C" void kernel_launch(void* const* d_in, const int* in_sizes, int n_in,
                              void* d_out, int out_size) {
    const float* x = (const float*)d_in[0];   // (16,32,256,256)
    const float* w = (const float*)d_in[1];   // (32,32,256,256)
    float* out = (float*)d_out;               // (16,32,256,256)

    float2 *Xf, *Kf, *Of;
    cudaGetSymbolAddress((void**)&Xf, g_Xf);
    cudaGetSymbolAddress((void**)&Kf, g_Kf);
    cudaGetSymbolAddress((void**)&Of, g_Of);

    cudaFuncSetAttribute(einsum_tc_kernel,
                         cudaFuncAttributeMaxDynamicSharedMemorySize, 65536);

    init_tw_kernel<<<1, 256>>>();

    // forward row FFTs (transposed write)
    rfft_rows_kernel<<<NB*NC*16, 256>>>(x, Xf);
    rfft_rows_kernel<<<NO*NC*16, 256>>>(w, Kf);
    // forward column FFTs (streaming, scrambled bin order)
    fft_cols_fwd_kernel<<<NB*NC*17, 256>>>(Xf);
    fft_cols_fwd_kernel<<<NO*NC*17, 256>>>(Kf);

    // frequency-domain channel contraction (512 thr, 1 bin/warp, f-tile 16)
    einsum_tc_kernel<<<FREQ/16, 512, 65536>>>(Xf, Kf, Of);

    // inverse column FFT (consumes scrambled order, 1/256)
    fft_cols_inv_kernel<<<NB*NO*17, 256>>>(Of, 1.0f/256.0f);
    // inverse row FFT (gathers transposed layout, final 1/256)
    irfft_rows_kernel<<<NB*NO*16, 256>>>(Of, out);
}